// round 8
// baseline (speedup 1.0000x reference)
#include <cuda_runtime.h>
#include <cuda_bf16.h>

#define N_NODES 50000
#define N_EDGES 800000
#define IN_DIM  128
#define HD      128   // N_HEAD * OUT_DIM
#define NHEAD   4
#define IN_E    16

#define SCAN_BS 512
#define NBLK_SCAN ((N_NODES + SCAN_BS - 1) / SCAN_BS)   // 98

// ---------------- scratch (__device__ globals; alloc-free rule) ----------------
__device__ float g_featn[(size_t)N_NODES * HD];
__device__ float g_el[N_NODES * NHEAD];
__device__ float g_er[N_NODES * NHEAD];
__device__ float g_lgs[(size_t)N_EDGES * NHEAD];  // leaky-relu logits, CSR order
__device__ int   g_srcs[N_EDGES];                 // src node per CSR slot
__device__ int   g_cnt[N_NODES];                  // in-degree histogram (zeroed by k_node)
__device__ int   g_off[N_NODES + 1];
__device__ int   g_cur[N_NODES];
__device__ int   g_menc[N_NODES * NHEAD];         // encoded segment max
__device__ int   g_tilectr;
__device__ unsigned long long g_tstat[NBLK_SCAN];

__device__ __forceinline__ int fenc(float f) {
    int b = __float_as_int(f);
    return b >= 0 ? b : (b ^ 0x7fffffff);
}
__device__ __forceinline__ float fdec(int b) {
    return __int_as_float(b >= 0 ? b : (b ^ 0x7fffffff));
}

typedef unsigned long long ull;
__device__ __forceinline__ void ffma2(ull& d, ull a, ull b) {
    asm("fma.rn.f32x2 %0, %1, %2, %0;" : "+l"(d) : "l"(a), "l"(b));
}
__device__ __forceinline__ ull addf2(ull a, ull b) {
    ull r; asm("add.rn.f32x2 %0, %1, %2;" : "=l"(r) : "l"(a), "l"(b)); return r;
}
__device__ __forceinline__ ull pack2(float v) {
    ull r; asm("mov.b64 %0, {%1, %1};" : "=l"(r) : "f"(v)); return r;
}

// ---------------- K0 (slot 0): histogram + per-run state init ----------------
__global__ void k_hist(const int* __restrict__ dst) {
    int i = blockIdx.x * blockDim.x + threadIdx.x;
    if (i == 0) g_tilectr = 0;
    if (i < NBLK_SCAN) g_tstat[i] = 0ull;
    if (i < N_NODES * NHEAD) g_menc[i] = (int)0x80000000;
    if (i < N_EDGES) atomicAdd(&g_cnt[dst[i]], 1);
}

// ---------------- K1 (slot 1): single-pass decoupled-lookback exclusive scan ----------------
__global__ void k_scan() {
    __shared__ int stile;
    __shared__ int swarp[16];
    __shared__ int sprefix;
    int t = threadIdx.x;
    if (t == 0) stile = atomicAdd(&g_tilectr, 1);
    __syncthreads();
    int tile = stile;
    int i = tile * SCAN_BS + t;
    int v = (i < N_NODES) ? g_cnt[i] : 0;

    int lane = t & 31, wid = t >> 5;
    int xv = v;
    #pragma unroll
    for (int o = 1; o < 32; o <<= 1) {
        int u = __shfl_up_sync(0xffffffffu, xv, o);
        if (lane >= o) xv += u;
    }
    if (lane == 31) swarp[wid] = xv;
    __syncthreads();
    if (wid == 0) {
        int y = (lane < 16) ? swarp[lane] : 0;
        #pragma unroll
        for (int o = 1; o < 16; o <<= 1) {
            int u = __shfl_up_sync(0xffffffffu, y, o);
            if (lane >= o) y += u;
        }
        if (lane < 16) swarp[lane] = y;
    }
    __syncthreads();
    int incl = xv + (wid ? swarp[wid - 1] : 0);
    int total = swarp[15];

    if (t == 0) {
        if (tile == 0) {
            __threadfence();
            atomicExch(&g_tstat[0], (2ull << 32) | (unsigned)total);
            sprefix = 0;
        } else {
            __threadfence();
            atomicExch(&g_tstat[tile], (1ull << 32) | (unsigned)total);
            int excl = 0;
            for (int tb = tile - 1; tb >= 0;) {
                unsigned long long s;
                do { s = atomicAdd(&g_tstat[tb], 0ull); } while ((s >> 32) == 0ull);
                excl += (int)(unsigned)s;
                if ((s >> 32) == 2ull) break;
                tb--;
            }
            __threadfence();
            atomicExch(&g_tstat[tile], (2ull << 32) | (unsigned)(excl + total));
            sprefix = excl;
        }
    }
    __syncthreads();
    int pre = sprefix;
    if (i < N_NODES) {
        int off = pre + incl - v;
        g_off[i] = off;
        g_cur[i] = off;
    }
    if (i == N_NODES - 1) g_off[N_NODES] = pre + incl;
}

// ---------------- K2/K3 (slots 2,3): split-K node projection SGEMM ----------------
// Per phase: 256 threads, block tile 128 nodes x 128 outs x 64 K.
// smem = 2 * 64 * 132 * 4 = 67584 B -> 3 blocks/SM = 24 warps. Slot 3 (phase 1) PROFILED.
#define GK   64
#define GSTR 132
__global__ void __launch_bounds__(256, 3)
k_gemm(const float* __restrict__ x, const float* __restrict__ W,
       int koff, int phase) {
    extern __shared__ float sm[];
    float* Wsm = sm;                    // [kl*132 + out]   64*132
    float* Xs  = sm + GK * GSTR;        // [kl*132 + n]     64*132
    int tid = threadIdx.x;
    int base = blockIdx.x * 128;

    // stage W panel: W[out][koff+kl] -> Wsm[kl][out]  (256B contiguous per row)
    for (int i = tid; i < 128 * GK; i += 256) {
        int out = i >> 6, kl = i & 63;
        Wsm[kl * GSTR + out] = W[out * IN_DIM + koff + kl];
    }
    // stage X panel: x[n][koff+kl] -> Xs[kl][n]
    for (int i = tid; i < 128 * GK; i += 256) {
        int n = i >> 6, kl = i & 63;
        int gn = base + n;
        Xs[kl * GSTR + n] = (gn < N_NODES) ? x[(size_t)gn * IN_DIM + koff + kl] : 0.0f;
    }
    __syncthreads();

    int ty = tid >> 4, tx = tid & 15;   // ty: 16 groups of 8 nodes, tx: 8 outs
    int n0 = ty * 8, c0 = tx * 8;
    ull acc[8][4];
    #pragma unroll
    for (int j = 0; j < 8; j++)
        #pragma unroll
        for (int p = 0; p < 4; p++) acc[j][p] = 0ull;

    #pragma unroll 2
    for (int kl = 0; kl < GK; kl++) {
        const float* xr = Xs  + kl * GSTR + n0;
        const float* wr = Wsm + kl * GSTR + c0;
        ulonglong2 w0 = *(const ulonglong2*)(wr);
        ulonglong2 w1 = *(const ulonglong2*)(wr + 4);
        float4 xa = *(const float4*)(xr);
        float4 xb = *(const float4*)(xr + 4);
        float xv[8] = {xa.x, xa.y, xa.z, xa.w, xb.x, xb.y, xb.z, xb.w};
        #pragma unroll
        for (int j = 0; j < 8; j++) {
            ull px = pack2(xv[j]);
            ffma2(acc[j][0], px, w0.x);
            ffma2(acc[j][1], px, w0.y);
            ffma2(acc[j][2], px, w1.x);
            ffma2(acc[j][3], px, w1.y);
        }
    }
    #pragma unroll
    for (int j = 0; j < 8; j++) {
        int node = base + n0 + j;
        if (node < N_NODES) {
            ull* o = (ull*)(g_featn + (size_t)node * HD + c0);
            if (phase) {                // add phase-0 partial (packed f32x2 adds)
                o[0] = addf2(acc[j][0], o[0]);
                o[1] = addf2(acc[j][1], o[1]);
                o[2] = addf2(acc[j][2], o[2]);
                o[3] = addf2(acc[j][3], o[3]);
            } else {
                o[0] = acc[j][0]; o[1] = acc[j][1];
                o[2] = acc[j][2]; o[3] = acc[j][3];
            }
        }
    }
}

// ---------------- K4: per-node attention logits el/er ----------------
__global__ void k_attn(const float* __restrict__ al, const float* __restrict__ ar) {
    int w = (blockIdx.x * blockDim.x + threadIdx.x) >> 5;
    if (w >= N_NODES) return;
    int lane = threadIdx.x & 31;
    int c = lane * 4, h = lane >> 3;
    float4 f = *(const float4*)(g_featn + (size_t)w * HD + c);
    float4 a = *(const float4*)(al + c);
    float4 b = *(const float4*)(ar + c);
    float pl = f.x * a.x + f.y * a.y + f.z * a.z + f.w * a.w;
    float pr = f.x * b.x + f.y * b.y + f.z * b.z + f.w * b.w;
    #pragma unroll
    for (int o = 1; o < 8; o <<= 1) {
        pl += __shfl_xor_sync(0xffffffffu, pl, o);
        pr += __shfl_xor_sync(0xffffffffu, pr, o);
    }
    if ((lane & 7) == 0) {
        g_el[w * NHEAD + h] = pl;
        g_er[w * NHEAD + h] = pr;
    }
}

// ---------------- K5: edge logits + CSR scatter + segment max ----------------
__global__ void k_logit(const float* __restrict__ fe, const int* __restrict__ src,
                        const int* __restrict__ dst, const float* __restrict__ ae) {
    __shared__ float aesm[NHEAD * IN_E];
    if (threadIdx.x < NHEAD * IN_E) aesm[threadIdx.x] = ae[threadIdx.x];
    __syncthreads();
    int e = blockIdx.x * blockDim.x + threadIdx.x;
    if (e >= N_EDGES) return;
    int s = src[e], d = dst[e];

    const float4* fr = (const float4*)(fe + (size_t)e * IN_E);
    float4 f0 = fr[0], f1 = fr[1], f2 = fr[2], f3 = fr[3];
    float4 elv = *(const float4*)(g_el + s * NHEAD);
    float4 erv = *(const float4*)(g_er + d * NHEAD);
    float els[4] = {elv.x, elv.y, elv.z, elv.w};
    float ers[4] = {erv.x, erv.y, erv.z, erv.w};

    float lg[4];
    #pragma unroll
    for (int h = 0; h < NHEAD; h++) {
        const float* a = aesm + h * IN_E;
        float ee = f0.x*a[0]  + f0.y*a[1]  + f0.z*a[2]  + f0.w*a[3]
                 + f1.x*a[4]  + f1.y*a[5]  + f1.z*a[6]  + f1.w*a[7]
                 + f2.x*a[8]  + f2.y*a[9]  + f2.z*a[10] + f2.w*a[11]
                 + f3.x*a[12] + f3.y*a[13] + f3.z*a[14] + f3.w*a[15];
        float v = els[h] + ers[h] + ee;
        lg[h] = v > 0.0f ? v : 0.2f * v;                // leaky relu 0.2
        atomicMax(&g_menc[d * NHEAD + h], fenc(lg[h]));
    }
    int pos = atomicAdd(&g_cur[d], 1);                  // CSR slot
    ((float4*)g_lgs)[pos] = make_float4(lg[0], lg[1], lg[2], lg[3]);
    g_srcs[pos] = s;
}

// ---------------- K6: per-dst-node softmax + weighted aggregate ----------------
__global__ void k_node(float* __restrict__ out) {
    int w = (blockIdx.x * blockDim.x + threadIdx.x) >> 5;
    if (w >= N_NODES) return;
    int lane = threadIdx.x & 31;
    if (lane == 0) g_cnt[w] = 0;                        // restore invariant for next run
    int c = lane * 4, h = lane >> 3;
    float* orow = out + (size_t)w * HD + c;

    int beg = g_off[w], end = g_off[w + 1];
    if (beg == end) {
        *(float4*)orow = make_float4(0.f, 0.f, 0.f, 0.f);
        return;
    }
    float mh = fdec(g_menc[w * NHEAD + h]);

    float sh0 = 0.f, sh1 = 0.f;
    float4 a0 = make_float4(0.f, 0.f, 0.f, 0.f);
    float4 a1 = make_float4(0.f, 0.f, 0.f, 0.f);
    const float* fb = g_featn + c;
    int p = beg;
    while (p < end) {
        int cnt = end - p; if (cnt > 32) cnt = 32;
        int sv = g_srcs[p + (lane < cnt ? lane : 0)];
        int j = 0;
        for (; j + 2 <= cnt; j += 2) {
            int s0 = __shfl_sync(0xffffffffu, sv, j);
            int s1 = __shfl_sync(0xffffffffu, sv, j + 1);
            float lg0 = g_lgs[(p + j) * NHEAD + h];
            float lg1 = g_lgs[(p + j + 1) * NHEAD + h];
            float4 f0 = *(const float4*)(fb + s0 * HD);
            float4 f1 = *(const float4*)(fb + s1 * HD);
            float e0 = __expf(lg0 - mh);
            float e1 = __expf(lg1 - mh);
            sh0 += e0; sh1 += e1;
            a0.x += e0 * f0.x; a0.y += e0 * f0.y; a0.z += e0 * f0.z; a0.w += e0 * f0.w;
            a1.x += e1 * f1.x; a1.y += e1 * f1.y; a1.z += e1 * f1.z; a1.w += e1 * f1.w;
        }
        if (j < cnt) {
            int s0 = __shfl_sync(0xffffffffu, sv, j);
            float lg0 = g_lgs[(p + j) * NHEAD + h];
            float4 f0 = *(const float4*)(fb + s0 * HD);
            float e0 = __expf(lg0 - mh);
            sh0 += e0;
            a0.x += e0 * f0.x; a0.y += e0 * f0.y; a0.z += e0 * f0.z; a0.w += e0 * f0.w;
        }
        p += cnt;
    }
    float inv = 1.0f / (sh0 + sh1);
    float4 acc = make_float4((a0.x + a1.x) * inv, (a0.y + a1.y) * inv,
                             (a0.z + a1.z) * inv, (a0.w + a1.w) * inv);
    *(float4*)orow = acc;
}

// ---------------- launch ----------------
extern "C" void kernel_launch(void* const* d_in, const int* in_sizes, int n_in,
                              void* d_out, int out_size) {
    const float* feats_node = (const float*)d_in[0];
    const float* feats_edge = (const float*)d_in[1];
    const int*   src        = (const int*)d_in[2];
    const int*   dst        = (const int*)d_in[3];
    const float* W_node     = (const float*)d_in[4];
    const float* attn_l     = (const float*)d_in[5];
    const float* attn_r     = (const float*)d_in[6];
    const float* attn_e     = (const float*)d_in[7];
    float* out = (float*)d_out;

    int gsm = 2 * GK * GSTR * sizeof(float);            // 67584 B
    static int configured = 0;
    if (!configured) {
        cudaFuncSetAttribute(k_gemm, cudaFuncAttributeMaxDynamicSharedMemorySize, gsm);
        configured = 1;
    }

    const int NBG = (N_NODES + 127) / 128;              // 391

    k_hist<<<(N_EDGES + 255) / 256, 256>>>(dst);                          // slot 0
    k_scan<<<NBLK_SCAN, SCAN_BS>>>();                                     // slot 1
    k_gemm<<<NBG, 256, gsm>>>(feats_node, W_node, 0, 0);                  // slot 2
    k_gemm<<<NBG, 256, gsm>>>(feats_node, W_node, GK, 1);                 // slot 3 (PROFILED)
    k_attn<<<(N_NODES * 32 + 255) / 256, 256>>>(attn_l, attn_r);          // slot 4
    k_logit<<<(N_EDGES + 255) / 256, 256>>>(feats_edge, src, dst, attn_e);
    k_node<<<(N_NODES * 32 + 255) / 256, 256>>>(out);
}

// round 10
// speedup vs baseline: 1.5521x; 1.5521x over previous
#include <cuda_runtime.h>
#include <cuda_bf16.h>

#define N_NODES 50000
#define N_EDGES 800000
#define IN_DIM  128
#define HD      128   // N_HEAD * OUT_DIM
#define NHEAD   4
#define IN_E    16

#define SCAN_BS 512
#define NBLK_SCAN ((N_NODES + SCAN_BS - 1) / SCAN_BS)   // 98

typedef unsigned int u32;
typedef unsigned long long ull;

// ---------------- scratch (__device__ globals; alloc-free rule) ----------------
__device__ float g_featn[(size_t)N_NODES * HD];
__device__ float g_el[N_NODES * NHEAD];
__device__ float g_er[N_NODES * NHEAD];
__device__ float g_lgs[(size_t)N_EDGES * NHEAD];  // leaky-relu logits, CSR order
__device__ int   g_srcs[N_EDGES];                 // src node per CSR slot
__device__ int   g_cnt[N_NODES];                  // in-degree histogram (zeroed by k_node)
__device__ int   g_off[N_NODES + 1];
__device__ int   g_cur[N_NODES];
__device__ int   g_menc[N_NODES * NHEAD];         // encoded segment max
__device__ int   g_tilectr;
__device__ ull   g_tstat[NBLK_SCAN];
// bf16-split GEMM operands
__device__ ull   g_xil[(size_t)N_NODES * 64];     // per row: 64 u64 = {hi bf16 pair | lo bf16 pair}
__device__ u32   g_whi[128 * 64];                 // W hi, packed bf16 pairs
__device__ u32   g_wlo[128 * 64];                 // W lo

__device__ __forceinline__ int fenc(float f) {
    int b = __float_as_int(f);
    return b >= 0 ? b : (b ^ 0x7fffffff);
}
__device__ __forceinline__ float fdec(int b) {
    return __int_as_float(b >= 0 ? b : (b ^ 0x7fffffff));
}

// ---------------- bf16 split helpers ----------------
__device__ __forceinline__ void split1(float x, unsigned short& h, unsigned short& l) {
    __nv_bfloat16 hb = __float2bfloat16(x);
    float r = x - __bfloat162float(hb);
    __nv_bfloat16 lb = __float2bfloat16(r);
    h = __bfloat16_as_ushort(hb);
    l = __bfloat16_as_ushort(lb);
}
__device__ __forceinline__ void split2(float a, float b, u32& hi, u32& lo) {
    unsigned short ha, la, hb, lb;
    split1(a, ha, la); split1(b, hb, lb);
    hi = (u32)ha | ((u32)hb << 16);
    lo = (u32)la | ((u32)lb << 16);
}

// ---------------- K0 (slot 0): convert X and W to bf16 hi/lo ----------------
#define XQUADS (N_NODES * IN_DIM / 4)   // 1,600,000
__global__ void k_cvt(const float* __restrict__ x, const float* __restrict__ W) {
    int i = blockIdx.x * blockDim.x + threadIdx.x;
    if (i < XQUADS) {
        float4 v = ((const float4*)x)[i];
        u32 h0, l0, h1, l1;
        split2(v.x, v.y, h0, l0);
        split2(v.z, v.w, h1, l1);
        g_xil[(size_t)i * 2]     = (ull)h0 | ((ull)l0 << 32);
        g_xil[(size_t)i * 2 + 1] = (ull)h1 | ((ull)l1 << 32);
    } else {
        int j = i - XQUADS;
        if (j < 128 * 128 / 4) {
            float4 v = ((const float4*)W)[j];
            u32 h0, l0, h1, l1;
            split2(v.x, v.y, h0, l0);
            split2(v.z, v.w, h1, l1);
            g_whi[j * 2] = h0;     g_wlo[j * 2] = l0;
            g_whi[j * 2 + 1] = h1; g_wlo[j * 2 + 1] = l1;
        }
    }
}

// ---------------- K1 (slot 1): histogram + per-run state init ----------------
__global__ void k_hist(const int* __restrict__ dst) {
    int i = blockIdx.x * blockDim.x + threadIdx.x;
    if (i == 0) g_tilectr = 0;
    if (i < NBLK_SCAN) g_tstat[i] = 0ull;
    if (i < N_NODES * NHEAD) g_menc[i] = (int)0x80000000;
    if (i < N_EDGES) atomicAdd(&g_cnt[dst[i]], 1);
}

// ---------------- K2 (slot 2): single-pass decoupled-lookback exclusive scan ----------------
__global__ void k_scan() {
    __shared__ int stile;
    __shared__ int swarp[16];
    __shared__ int sprefix;
    int t = threadIdx.x;
    if (t == 0) stile = atomicAdd(&g_tilectr, 1);
    __syncthreads();
    int tile = stile;
    int i = tile * SCAN_BS + t;
    int v = (i < N_NODES) ? g_cnt[i] : 0;

    int lane = t & 31, wid = t >> 5;
    int xv = v;
    #pragma unroll
    for (int o = 1; o < 32; o <<= 1) {
        int u = __shfl_up_sync(0xffffffffu, xv, o);
        if (lane >= o) xv += u;
    }
    if (lane == 31) swarp[wid] = xv;
    __syncthreads();
    if (wid == 0) {
        int y = (lane < 16) ? swarp[lane] : 0;
        #pragma unroll
        for (int o = 1; o < 16; o <<= 1) {
            int u = __shfl_up_sync(0xffffffffu, y, o);
            if (lane >= o) y += u;
        }
        if (lane < 16) swarp[lane] = y;
    }
    __syncthreads();
    int incl = xv + (wid ? swarp[wid - 1] : 0);
    int total = swarp[15];

    if (t == 0) {
        if (tile == 0) {
            __threadfence();
            atomicExch(&g_tstat[0], (2ull << 32) | (unsigned)total);
            sprefix = 0;
        } else {
            __threadfence();
            atomicExch(&g_tstat[tile], (1ull << 32) | (unsigned)total);
            int excl = 0;
            for (int tb = tile - 1; tb >= 0;) {
                ull s;
                do { s = atomicAdd(&g_tstat[tb], 0ull); } while ((s >> 32) == 0ull);
                excl += (int)(unsigned)s;
                if ((s >> 32) == 2ull) break;
                tb--;
            }
            __threadfence();
            atomicExch(&g_tstat[tile], (2ull << 32) | (unsigned)(excl + total));
            sprefix = excl;
        }
    }
    __syncthreads();
    int pre = sprefix;
    if (i < N_NODES) {
        int off = pre + incl - v;
        g_off[i] = off;
        g_cur[i] = off;
    }
    if (i == N_NODES - 1) g_off[N_NODES] = pre + incl;
}

// ---------------- K3 (slot 3, PROFILED): tensor-core projection GEMM ----------------
// bf16-split 3-mma trick: C = Ahi*Bhi + Ahi*Blo + Alo*Bhi (fp32 accum).
// 256 threads / 8 warps; block tile 128 nodes x 128 cols; warp tile 32x64.
// W staged in smem padded to 68 u32/row -> conflict-free fragment loads.
__device__ __forceinline__ void mma_bf16(float c[4], const u32 a[4], u32 b0, u32 b1) {
    asm volatile(
        "mma.sync.aligned.m16n8k16.row.col.f32.bf16.bf16.f32 "
        "{%0,%1,%2,%3},{%4,%5,%6,%7},{%8,%9},{%0,%1,%2,%3};"
        : "+f"(c[0]), "+f"(c[1]), "+f"(c[2]), "+f"(c[3])
        : "r"(a[0]), "r"(a[1]), "r"(a[2]), "r"(a[3]), "r"(b0), "r"(b1));
}

__global__ void __launch_bounds__(256, 2) k_mma() {
    extern __shared__ u32 smw[];
    u32* WH = smw;                  // [128][68]
    u32* WL = smw + 128 * 68;
    int tid = threadIdx.x;
    for (int i = tid; i < 128 * 64; i += 256) {
        int r = i >> 6, p = i & 63;
        WH[r * 68 + p] = g_whi[i];
        WL[r * 68 + p] = g_wlo[i];
    }
    __syncthreads();

    int warp = tid >> 5, lane = tid & 31;
    int g = lane >> 2, t = lane & 3;
    int mw = warp >> 1, nw = warp & 1;
    int m0 = blockIdx.x * 128 + mw * 32;
    int n0 = nw * 64;

    float c[2][8][4];
    #pragma unroll
    for (int mi = 0; mi < 2; mi++)
        #pragma unroll
        for (int nf = 0; nf < 8; nf++)
            #pragma unroll
            for (int q = 0; q < 4; q++) c[mi][nf][q] = 0.0f;

    for (int ks = 0; ks < 8; ks++) {
        u32 ahi[2][4], alo[2][4];
        #pragma unroll
        for (int mi = 0; mi < 2; mi++) {
            int r1 = m0 + mi * 16 + g;
            int r2 = r1 + 8;
            if (r1 >= N_NODES) r1 = N_NODES - 1;   // clamped rows only feed C rows >= N (unstored)
            if (r2 >= N_NODES) r2 = N_NODES - 1;
            const ull* p1 = g_xil + (size_t)r1 * 64 + ks * 8 + t;
            const ull* p2 = g_xil + (size_t)r2 * 64 + ks * 8 + t;
            ull A0 = p1[0], A1 = p2[0], A2 = p1[4], A3 = p2[4];
            ahi[mi][0] = (u32)A0; alo[mi][0] = (u32)(A0 >> 32);
            ahi[mi][1] = (u32)A1; alo[mi][1] = (u32)(A1 >> 32);
            ahi[mi][2] = (u32)A2; alo[mi][2] = (u32)(A2 >> 32);
            ahi[mi][3] = (u32)A3; alo[mi][3] = (u32)(A3 >> 32);
        }
        #pragma unroll
        for (int nf = 0; nf < 8; nf++) {
            int n = n0 + nf * 8 + g;
            int bi = n * 68 + ks * 8 + t;
            u32 bh0 = WH[bi], bh1 = WH[bi + 4];
            u32 bl0 = WL[bi], bl1 = WL[bi + 4];
            mma_bf16(c[0][nf], ahi[0], bh0, bh1);
            mma_bf16(c[1][nf], ahi[1], bh0, bh1);
            mma_bf16(c[0][nf], alo[0], bh0, bh1);
            mma_bf16(c[1][nf], alo[1], bh0, bh1);
            mma_bf16(c[0][nf], ahi[0], bl0, bl1);
            mma_bf16(c[1][nf], ahi[1], bl0, bl1);
        }
    }
    #pragma unroll
    for (int mi = 0; mi < 2; mi++) {
        int r1 = m0 + mi * 16 + g;
        int r2 = r1 + 8;
        #pragma unroll
        for (int nf = 0; nf < 8; nf++) {
            int col = n0 + nf * 8 + 2 * t;
            if (r1 < N_NODES)
                *(float2*)&g_featn[(size_t)r1 * HD + col] = make_float2(c[mi][nf][0], c[mi][nf][1]);
            if (r2 < N_NODES)
                *(float2*)&g_featn[(size_t)r2 * HD + col] = make_float2(c[mi][nf][2], c[mi][nf][3]);
        }
    }
}

// ---------------- K4: per-node attention logits el/er ----------------
__global__ void k_attn(const float* __restrict__ al, const float* __restrict__ ar) {
    int w = (blockIdx.x * blockDim.x + threadIdx.x) >> 5;
    if (w >= N_NODES) return;
    int lane = threadIdx.x & 31;
    int c = lane * 4, h = lane >> 3;
    float4 f = *(const float4*)(g_featn + (size_t)w * HD + c);
    float4 a = *(const float4*)(al + c);
    float4 b = *(const float4*)(ar + c);
    float pl = f.x * a.x + f.y * a.y + f.z * a.z + f.w * a.w;
    float pr = f.x * b.x + f.y * b.y + f.z * b.z + f.w * b.w;
    #pragma unroll
    for (int o = 1; o < 8; o <<= 1) {
        pl += __shfl_xor_sync(0xffffffffu, pl, o);
        pr += __shfl_xor_sync(0xffffffffu, pr, o);
    }
    if ((lane & 7) == 0) {
        g_el[w * NHEAD + h] = pl;
        g_er[w * NHEAD + h] = pr;
    }
}

// ---------------- K5: edge logits + CSR scatter + segment max ----------------
__global__ void k_logit(const float* __restrict__ fe, const int* __restrict__ src,
                        const int* __restrict__ dst, const float* __restrict__ ae) {
    __shared__ float aesm[NHEAD * IN_E];
    if (threadIdx.x < NHEAD * IN_E) aesm[threadIdx.x] = ae[threadIdx.x];
    __syncthreads();
    int e = blockIdx.x * blockDim.x + threadIdx.x;
    if (e >= N_EDGES) return;
    int s = src[e], d = dst[e];

    const float4* fr = (const float4*)(fe + (size_t)e * IN_E);
    float4 f0 = fr[0], f1 = fr[1], f2 = fr[2], f3 = fr[3];
    float4 elv = *(const float4*)(g_el + s * NHEAD);
    float4 erv = *(const float4*)(g_er + d * NHEAD);
    float els[4] = {elv.x, elv.y, elv.z, elv.w};
    float ers[4] = {erv.x, erv.y, erv.z, erv.w};

    float lg[4];
    #pragma unroll
    for (int h = 0; h < NHEAD; h++) {
        const float* a = aesm + h * IN_E;
        float ee = f0.x*a[0]  + f0.y*a[1]  + f0.z*a[2]  + f0.w*a[3]
                 + f1.x*a[4]  + f1.y*a[5]  + f1.z*a[6]  + f1.w*a[7]
                 + f2.x*a[8]  + f2.y*a[9]  + f2.z*a[10] + f2.w*a[11]
                 + f3.x*a[12] + f3.y*a[13] + f3.z*a[14] + f3.w*a[15];
        float v = els[h] + ers[h] + ee;
        lg[h] = v > 0.0f ? v : 0.2f * v;                // leaky relu 0.2
        atomicMax(&g_menc[d * NHEAD + h], fenc(lg[h]));
    }
    int pos = atomicAdd(&g_cur[d], 1);                  // CSR slot
    ((float4*)g_lgs)[pos] = make_float4(lg[0], lg[1], lg[2], lg[3]);
    g_srcs[pos] = s;
}

// ---------------- K6: per-dst-node softmax + weighted aggregate ----------------
__global__ void k_node(float* __restrict__ out) {
    int w = (blockIdx.x * blockDim.x + threadIdx.x) >> 5;
    if (w >= N_NODES) return;
    int lane = threadIdx.x & 31;
    if (lane == 0) g_cnt[w] = 0;                        // restore invariant for next run
    int c = lane * 4, h = lane >> 3;
    float* orow = out + (size_t)w * HD + c;

    int beg = g_off[w], end = g_off[w + 1];
    if (beg == end) {
        *(float4*)orow = make_float4(0.f, 0.f, 0.f, 0.f);
        return;
    }
    float mh = fdec(g_menc[w * NHEAD + h]);

    float sh0 = 0.f, sh1 = 0.f;
    float4 a0 = make_float4(0.f, 0.f, 0.f, 0.f);
    float4 a1 = make_float4(0.f, 0.f, 0.f, 0.f);
    const float* fb = g_featn + c;
    int p = beg;
    while (p < end) {
        int cnt = end - p; if (cnt > 32) cnt = 32;
        int sv = g_srcs[p + (lane < cnt ? lane : 0)];
        int j = 0;
        for (; j + 2 <= cnt; j += 2) {
            int s0 = __shfl_sync(0xffffffffu, sv, j);
            int s1 = __shfl_sync(0xffffffffu, sv, j + 1);
            float lg0 = g_lgs[(p + j) * NHEAD + h];
            float lg1 = g_lgs[(p + j + 1) * NHEAD + h];
            float4 f0 = *(const float4*)(fb + s0 * HD);
            float4 f1 = *(const float4*)(fb + s1 * HD);
            float e0 = __expf(lg0 - mh);
            float e1 = __expf(lg1 - mh);
            sh0 += e0; sh1 += e1;
            a0.x += e0 * f0.x; a0.y += e0 * f0.y; a0.z += e0 * f0.z; a0.w += e0 * f0.w;
            a1.x += e1 * f1.x; a1.y += e1 * f1.y; a1.z += e1 * f1.z; a1.w += e1 * f1.w;
        }
        if (j < cnt) {
            int s0 = __shfl_sync(0xffffffffu, sv, j);
            float lg0 = g_lgs[(p + j) * NHEAD + h];
            float4 f0 = *(const float4*)(fb + s0 * HD);
            float e0 = __expf(lg0 - mh);
            sh0 += e0;
            a0.x += e0 * f0.x; a0.y += e0 * f0.y; a0.z += e0 * f0.z; a0.w += e0 * f0.w;
        }
        p += cnt;
    }
    float inv = 1.0f / (sh0 + sh1);
    float4 acc = make_float4((a0.x + a1.x) * inv, (a0.y + a1.y) * inv,
                             (a0.z + a1.z) * inv, (a0.w + a1.w) * inv);
    *(float4*)orow = acc;
}

// ---------------- launch ----------------
extern "C" void kernel_launch(void* const* d_in, const int* in_sizes, int n_in,
                              void* d_out, int out_size) {
    const float* feats_node = (const float*)d_in[0];
    const float* feats_edge = (const float*)d_in[1];
    const int*   src        = (const int*)d_in[2];
    const int*   dst        = (const int*)d_in[3];
    const float* W_node     = (const float*)d_in[4];
    const float* attn_l     = (const float*)d_in[5];
    const float* attn_r     = (const float*)d_in[6];
    const float* attn_e     = (const float*)d_in[7];
    float* out = (float*)d_out;

    int msm = 2 * 128 * 68 * sizeof(u32);               // 69632 B
    static int configured = 0;
    if (!configured) {
        cudaFuncSetAttribute(k_mma, cudaFuncAttributeMaxDynamicSharedMemorySize, msm);
        configured = 1;
    }

    int cvt_threads = XQUADS + 128 * 128 / 4;
    k_cvt<<<(cvt_threads + 255) / 256, 256>>>(feats_node, W_node);        // slot 0
    k_hist<<<(N_EDGES + 255) / 256, 256>>>(dst);                          // slot 1
    k_scan<<<NBLK_SCAN, SCAN_BS>>>();                                     // slot 2
    k_mma<<<(N_NODES + 127) / 128, 256, msm>>>();                         // slot 3 (PROFILED)
    k_attn<<<(N_NODES * 32 + 255) / 256, 256>>>(attn_l, attn_r);          // slot 4
    k_logit<<<(N_EDGES + 255) / 256, 256>>>(feats_edge, src, dst, attn_e);
    k_node<<<(N_NODES * 32 + 255) / 256, 256>>>(out);
}

// round 13
// speedup vs baseline: 1.6891x; 1.0883x over previous
#include <cuda_runtime.h>
#include <cuda_bf16.h>

#define N_NODES 50000
#define N_EDGES 800000
#define IN_DIM  128
#define HD      128   // N_HEAD * OUT_DIM
#define NHEAD   4
#define IN_E    16

#define SCAN_BS 512
#define NBLK_SCAN ((N_NODES + SCAN_BS - 1) / SCAN_BS)   // 98

typedef unsigned int u32;
typedef unsigned long long ull;

// ---------------- scratch (__device__ globals; alloc-free rule) ----------------
__device__ float g_featn[(size_t)N_NODES * HD];
__device__ float g_el[N_NODES * NHEAD];
__device__ float g_er[N_NODES * NHEAD];
__device__ float g_lgs[(size_t)N_EDGES * NHEAD];  // leaky-relu logits, CSR order
__device__ int   g_srcs[N_EDGES];                 // src node per CSR slot
__device__ int   g_cnt[N_NODES];                  // in-degree histogram (zeroed by k_node)
__device__ int   g_off[N_NODES + 1];
__device__ int   g_cur[N_NODES];
__device__ int   g_menc[N_NODES * NHEAD];         // encoded segment max
__device__ int   g_tilectr;
__device__ ull   g_tstat[NBLK_SCAN];
// bf16-split GEMM operands
__device__ ull   g_xil[(size_t)N_NODES * 64];     // per row: 64 u64 = {hi bf16 pair | lo bf16 pair}
__device__ u32   g_whi[128 * 64];                 // W hi, packed bf16 pairs
__device__ u32   g_wlo[128 * 64];                 // W lo

__device__ __forceinline__ int fenc(float f) {
    int b = __float_as_int(f);
    return b >= 0 ? b : (b ^ 0x7fffffff);
}
__device__ __forceinline__ float fdec(int b) {
    return __int_as_float(b >= 0 ? b : (b ^ 0x7fffffff));
}

// ---------------- bf16 split helpers ----------------
__device__ __forceinline__ void split1(float x, unsigned short& h, unsigned short& l) {
    __nv_bfloat16 hb = __float2bfloat16(x);
    float r = x - __bfloat162float(hb);
    __nv_bfloat16 lb = __float2bfloat16(r);
    h = __bfloat16_as_ushort(hb);
    l = __bfloat16_as_ushort(lb);
}
__device__ __forceinline__ void split2(float a, float b, u32& hi, u32& lo) {
    unsigned short ha, la, hb, lb;
    split1(a, ha, la); split1(b, hb, lb);
    hi = (u32)ha | ((u32)hb << 16);
    lo = (u32)la | ((u32)lb << 16);
}

// ---------------- K0 (slot 0): cvt X/W to bf16 hi/lo + histogram + state init ----------------
#define XQUADS (N_NODES * IN_DIM / 4)   // 1,600,000
__global__ void k_prep(const float* __restrict__ x, const float* __restrict__ W,
                       const int* __restrict__ dst) {
    int i = blockIdx.x * blockDim.x + threadIdx.x;
    if (i == 0) g_tilectr = 0;
    if (i < NBLK_SCAN) g_tstat[i] = 0ull;
    if (i < N_NODES * NHEAD) g_menc[i] = (int)0x80000000;
    if (i < N_EDGES) atomicAdd(&g_cnt[dst[i]], 1);
    if (i < XQUADS) {
        float4 v = ((const float4*)x)[i];
        u32 h0, l0, h1, l1;
        split2(v.x, v.y, h0, l0);
        split2(v.z, v.w, h1, l1);
        g_xil[(size_t)i * 2]     = (ull)h0 | ((ull)l0 << 32);
        g_xil[(size_t)i * 2 + 1] = (ull)h1 | ((ull)l1 << 32);
    } else {
        int j = i - XQUADS;
        if (j < 128 * 128 / 4) {
            float4 v = ((const float4*)W)[j];
            u32 h0, l0, h1, l1;
            split2(v.x, v.y, h0, l0);
            split2(v.z, v.w, h1, l1);
            g_whi[j * 2] = h0;     g_wlo[j * 2] = l0;
            g_whi[j * 2 + 1] = h1; g_wlo[j * 2 + 1] = l1;
        }
    }
}

// ---------------- K1 (slot 1): single-pass decoupled-lookback exclusive scan ----------------
__global__ void k_scan() {
    __shared__ int stile;
    __shared__ int swarp[16];
    __shared__ int sprefix;
    int t = threadIdx.x;
    if (t == 0) stile = atomicAdd(&g_tilectr, 1);
    __syncthreads();
    int tile = stile;
    int i = tile * SCAN_BS + t;
    int v = (i < N_NODES) ? g_cnt[i] : 0;

    int lane = t & 31, wid = t >> 5;
    int xv = v;
    #pragma unroll
    for (int o = 1; o < 32; o <<= 1) {
        int u = __shfl_up_sync(0xffffffffu, xv, o);
        if (lane >= o) xv += u;
    }
    if (lane == 31) swarp[wid] = xv;
    __syncthreads();
    if (wid == 0) {
        int y = (lane < 16) ? swarp[lane] : 0;
        #pragma unroll
        for (int o = 1; o < 16; o <<= 1) {
            int u = __shfl_up_sync(0xffffffffu, y, o);
            if (lane >= o) y += u;
        }
        if (lane < 16) swarp[lane] = y;
    }
    __syncthreads();
    int incl = xv + (wid ? swarp[wid - 1] : 0);
    int total = swarp[15];

    if (t == 0) {
        if (tile == 0) {
            __threadfence();
            atomicExch(&g_tstat[0], (2ull << 32) | (unsigned)total);
            sprefix = 0;
        } else {
            __threadfence();
            atomicExch(&g_tstat[tile], (1ull << 32) | (unsigned)total);
            int excl = 0;
            for (int tb = tile - 1; tb >= 0;) {
                ull s;
                do { s = atomicAdd(&g_tstat[tb], 0ull); } while ((s >> 32) == 0ull);
                excl += (int)(unsigned)s;
                if ((s >> 32) == 2ull) break;
                tb--;
            }
            __threadfence();
            atomicExch(&g_tstat[tile], (2ull << 32) | (unsigned)(excl + total));
            sprefix = excl;
        }
    }
    __syncthreads();
    int pre = sprefix;
    if (i < N_NODES) {
        int off = pre + incl - v;
        g_off[i] = off;
        g_cur[i] = off;
    }
    if (i == N_NODES - 1) g_off[N_NODES] = pre + incl;
}

// ---------------- K2 (slot 2): tensor-core GEMM + fused el/er epilogue ----------------
// bf16-split 3-mma: C = Ahi*Bhi + Alo*Bhi + Ahi*Blo (fp32 accum).
// 256 threads / 8 warps; block tile 128x128; warp tile 32x64; A loads double-buffered.
__device__ __forceinline__ void mma_bf16(float c[4], const u32 a[4], u32 b0, u32 b1) {
    asm volatile(
        "mma.sync.aligned.m16n8k16.row.col.f32.bf16.bf16.f32 "
        "{%0,%1,%2,%3},{%4,%5,%6,%7},{%8,%9},{%0,%1,%2,%3};"
        : "+f"(c[0]), "+f"(c[1]), "+f"(c[2]), "+f"(c[3])
        : "r"(a[0]), "r"(a[1]), "r"(a[2]), "r"(a[3]), "r"(b0), "r"(b1));
}

__global__ void __launch_bounds__(256, 2)
k_mma(const float* __restrict__ al, const float* __restrict__ ar) {
    extern __shared__ u32 smw[];
    u32* WH = smw;                  // [128][68]
    u32* WL = smw + 128 * 68;
    int tid = threadIdx.x;
    for (int i = tid; i < 128 * 64; i += 256) {
        int r = i >> 6, p = i & 63;
        WH[r * 68 + p] = g_whi[i];
        WL[r * 68 + p] = g_wlo[i];
    }
    __syncthreads();

    int warp = tid >> 5, lane = tid & 31;
    int g = lane >> 2, t = lane & 3;
    int mw = warp >> 1, nw = warp & 1;
    int m0 = blockIdx.x * 128 + mw * 32;
    int n0 = nw * 64;

    // clamped A row pointers (clamped rows only feed unstored C rows)
    int r1a = m0 + g;       if (r1a >= N_NODES) r1a = N_NODES - 1;
    int r2a = r1a + 8;      if (r2a >= N_NODES) r2a = N_NODES - 1;
    int r1b = m0 + 16 + g;  if (r1b >= N_NODES) r1b = N_NODES - 1;
    int r2b = r1b + 8;      if (r2b >= N_NODES) r2b = N_NODES - 1;
    const ull* pr[4] = { g_xil + (size_t)r1a * 64 + t, g_xil + (size_t)r2a * 64 + t,
                         g_xil + (size_t)r1b * 64 + t, g_xil + (size_t)r2b * 64 + t };

    float c[2][8][4];
    #pragma unroll
    for (int mi = 0; mi < 2; mi++)
        #pragma unroll
        for (int nf = 0; nf < 8; nf++)
            #pragma unroll
            for (int q = 0; q < 4; q++) c[mi][nf][q] = 0.0f;

    u32 ahi[2][4], alo[2][4];
    #pragma unroll
    for (int mi = 0; mi < 2; mi++) {
        ull A0 = pr[mi*2][0], A1 = pr[mi*2+1][0], A2 = pr[mi*2][4], A3 = pr[mi*2+1][4];
        ahi[mi][0] = (u32)A0; alo[mi][0] = (u32)(A0 >> 32);
        ahi[mi][1] = (u32)A1; alo[mi][1] = (u32)(A1 >> 32);
        ahi[mi][2] = (u32)A2; alo[mi][2] = (u32)(A2 >> 32);
        ahi[mi][3] = (u32)A3; alo[mi][3] = (u32)(A3 >> 32);
    }

    for (int ks = 0; ks < 8; ks++) {
        u32 nhi[2][4], nlo[2][4];
        if (ks < 7) {                       // prefetch next K-slab while MMAing this one
            int o = (ks + 1) * 8;
            #pragma unroll
            for (int mi = 0; mi < 2; mi++) {
                ull A0 = pr[mi*2][o], A1 = pr[mi*2+1][o], A2 = pr[mi*2][o+4], A3 = pr[mi*2+1][o+4];
                nhi[mi][0] = (u32)A0; nlo[mi][0] = (u32)(A0 >> 32);
                nhi[mi][1] = (u32)A1; nlo[mi][1] = (u32)(A1 >> 32);
                nhi[mi][2] = (u32)A2; nlo[mi][2] = (u32)(A2 >> 32);
                nhi[mi][3] = (u32)A3; nlo[mi][3] = (u32)(A3 >> 32);
            }
        }
        #pragma unroll
        for (int nf = 0; nf < 8; nf++) {
            int n = n0 + nf * 8 + g;
            int bi = n * 68 + ks * 8 + t;
            u32 bh0 = WH[bi], bh1 = WH[bi + 4];
            u32 bl0 = WL[bi], bl1 = WL[bi + 4];
            mma_bf16(c[0][nf], ahi[0], bh0, bh1);
            mma_bf16(c[1][nf], ahi[1], bh0, bh1);
            mma_bf16(c[0][nf], alo[0], bh0, bh1);
            mma_bf16(c[1][nf], alo[1], bh0, bh1);
            mma_bf16(c[0][nf], ahi[0], bl0, bl1);
            mma_bf16(c[1][nf], ahi[1], bl0, bl1);
        }
        #pragma unroll
        for (int mi = 0; mi < 2; mi++)
            #pragma unroll
            for (int q = 0; q < 4; q++) { ahi[mi][q] = nhi[mi][q]; alo[mi][q] = nlo[mi][q]; }
    }

    // store featn
    #pragma unroll
    for (int mi = 0; mi < 2; mi++) {
        int r1 = m0 + mi * 16 + g;
        int r2 = r1 + 8;
        #pragma unroll
        for (int nf = 0; nf < 8; nf++) {
            int col = n0 + nf * 8 + 2 * t;
            if (r1 < N_NODES)
                *(float2*)&g_featn[(size_t)r1 * HD + col] = make_float2(c[mi][nf][0], c[mi][nf][1]);
            if (r2 < N_NODES)
                *(float2*)&g_featn[(size_t)r2 * HD + col] = make_float2(c[mi][nf][2], c[mi][nf][3]);
        }
    }

    // ---- fused el/er epilogue: per (row, head) dot over the warp's 32-col head slice ----
    #pragma unroll
    for (int mi = 0; mi < 2; mi++) {
        #pragma unroll
        for (int hh = 0; hh < 2; hh++) {
            float p1l = 0.f, p2l = 0.f, p1r = 0.f, p2r = 0.f;
            #pragma unroll
            for (int nf = hh * 4; nf < hh * 4 + 4; nf++) {
                int col = n0 + nf * 8 + 2 * t;
                float a0v = al[col], a1v = al[col + 1];
                float b0v = ar[col], b1v = ar[col + 1];
                p1l += c[mi][nf][0] * a0v + c[mi][nf][1] * a1v;
                p2l += c[mi][nf][2] * a0v + c[mi][nf][3] * a1v;
                p1r += c[mi][nf][0] * b0v + c[mi][nf][1] * b1v;
                p2r += c[mi][nf][2] * b0v + c[mi][nf][3] * b1v;
            }
            // quad reduce over t (lane bits 0,1)
            #pragma unroll
            for (int o = 1; o <= 2; o <<= 1) {
                p1l += __shfl_xor_sync(0xffffffffu, p1l, o);
                p2l += __shfl_xor_sync(0xffffffffu, p2l, o);
                p1r += __shfl_xor_sync(0xffffffffu, p1r, o);
                p2r += __shfl_xor_sync(0xffffffffu, p2r, o);
            }
            if (t == 0) {
                int head = 2 * nw + hh;
                int r1 = m0 + mi * 16 + g;
                int r2 = r1 + 8;
                if (r1 < N_NODES) { g_el[r1 * NHEAD + head] = p1l; g_er[r1 * NHEAD + head] = p1r; }
                if (r2 < N_NODES) { g_el[r2 * NHEAD + head] = p2l; g_er[r2 * NHEAD + head] = p2r; }
            }
        }
    }
}

// ---------------- K3 (slot 3, PROFILED): edge logits + CSR scatter + segment max ----------------
__global__ void k_logit(const float* __restrict__ fe, const int* __restrict__ src,
                        const int* __restrict__ dst, const float* __restrict__ ae) {
    __shared__ float aesm[NHEAD * IN_E];
    if (threadIdx.x < NHEAD * IN_E) aesm[threadIdx.x] = ae[threadIdx.x];
    __syncthreads();
    int e = blockIdx.x * blockDim.x + threadIdx.x;
    if (e >= N_EDGES) return;
    int s = src[e], d = dst[e];

    const float4* fr = (const float4*)(fe + (size_t)e * IN_E);
    float4 f0 = fr[0], f1 = fr[1], f2 = fr[2], f3 = fr[3];
    float4 elv = *(const float4*)(g_el + s * NHEAD);
    float4 erv = *(const float4*)(g_er + d * NHEAD);
    float els[4] = {elv.x, elv.y, elv.z, elv.w};
    float ers[4] = {erv.x, erv.y, erv.z, erv.w};

    float lg[4];
    #pragma unroll
    for (int h = 0; h < NHEAD; h++) {
        const float* a = aesm + h * IN_E;
        float ee = f0.x*a[0]  + f0.y*a[1]  + f0.z*a[2]  + f0.w*a[3]
                 + f1.x*a[4]  + f1.y*a[5]  + f1.z*a[6]  + f1.w*a[7]
                 + f2.x*a[8]  + f2.y*a[9]  + f2.z*a[10] + f2.w*a[11]
                 + f3.x*a[12] + f3.y*a[13] + f3.z*a[14] + f3.w*a[15];
        float v = els[h] + ers[h] + ee;
        lg[h] = v > 0.0f ? v : 0.2f * v;                // leaky relu 0.2
        atomicMax(&g_menc[d * NHEAD + h], fenc(lg[h]));
    }
    int pos = atomicAdd(&g_cur[d], 1);                  // CSR slot
    ((float4*)g_lgs)[pos] = make_float4(lg[0], lg[1], lg[2], lg[3]);
    g_srcs[pos] = s;
}

// ---------------- K4: per-dst-node softmax + weighted aggregate ----------------
__global__ void k_node(float* __restrict__ out) {
    int w = (blockIdx.x * blockDim.x + threadIdx.x) >> 5;
    if (w >= N_NODES) return;
    int lane = threadIdx.x & 31;
    if (lane == 0) g_cnt[w] = 0;                        // restore invariant for next run
    int c = lane * 4, h = lane >> 3;
    float* orow = out + (size_t)w * HD + c;

    int beg = g_off[w], end = g_off[w + 1];
    if (beg == end) {
        *(float4*)orow = make_float4(0.f, 0.f, 0.f, 0.f);
        return;
    }
    float mh = fdec(g_menc[w * NHEAD + h]);

    float sh0 = 0.f, sh1 = 0.f;
    float4 a0 = make_float4(0.f, 0.f, 0.f, 0.f);
    float4 a1 = make_float4(0.f, 0.f, 0.f, 0.f);
    const float* fb = g_featn + c;
    int p = beg;
    while (p < end) {
        int cnt = end - p; if (cnt > 32) cnt = 32;
        int sv = g_srcs[p + (lane < cnt ? lane : 0)];
        int j = 0;
        for (; j + 2 <= cnt; j += 2) {
            int s0 = __shfl_sync(0xffffffffu, sv, j);
            int s1 = __shfl_sync(0xffffffffu, sv, j + 1);
            float lg0 = g_lgs[(p + j) * NHEAD + h];
            float lg1 = g_lgs[(p + j + 1) * NHEAD + h];
            float4 f0 = *(const float4*)(fb + s0 * HD);
            float4 f1 = *(const float4*)(fb + s1 * HD);
            float e0 = __expf(lg0 - mh);
            float e1 = __expf(lg1 - mh);
            sh0 += e0; sh1 += e1;
            a0.x += e0 * f0.x; a0.y += e0 * f0.y; a0.z += e0 * f0.z; a0.w += e0 * f0.w;
            a1.x += e1 * f1.x; a1.y += e1 * f1.y; a1.z += e1 * f1.z; a1.w += e1 * f1.w;
        }
        if (j < cnt) {
            int s0 = __shfl_sync(0xffffffffu, sv, j);
            float lg0 = g_lgs[(p + j) * NHEAD + h];
            float4 f0 = *(const float4*)(fb + s0 * HD);
            float e0 = __expf(lg0 - mh);
            sh0 += e0;
            a0.x += e0 * f0.x; a0.y += e0 * f0.y; a0.z += e0 * f0.z; a0.w += e0 * f0.w;
        }
        p += cnt;
    }
    float inv = 1.0f / (sh0 + sh1);
    float4 acc = make_float4((a0.x + a1.x) * inv, (a0.y + a1.y) * inv,
                             (a0.z + a1.z) * inv, (a0.w + a1.w) * inv);
    *(float4*)orow = acc;
}

// ---------------- launch ----------------
extern "C" void kernel_launch(void* const* d_in, const int* in_sizes, int n_in,
                              void* d_out, int out_size) {
    const float* feats_node = (const float*)d_in[0];
    const float* feats_edge = (const float*)d_in[1];
    const int*   src        = (const int*)d_in[2];
    const int*   dst        = (const int*)d_in[3];
    const float* W_node     = (const float*)d_in[4];
    const float* attn_l     = (const float*)d_in[5];
    const float* attn_r     = (const float*)d_in[6];
    const float* attn_e     = (const float*)d_in[7];
    float* out = (float*)d_out;

    int msm = 2 * 128 * 68 * sizeof(u32);               // 69632 B
    static int configured = 0;
    if (!configured) {
        cudaFuncSetAttribute(k_mma, cudaFuncAttributeMaxDynamicSharedMemorySize, msm);
        configured = 1;
    }

    int prep_threads = XQUADS + 128 * 128 / 4;
    k_prep<<<(prep_threads + 255) / 256, 256>>>(feats_node, W_node, dst);   // slot 0
    k_scan<<<NBLK_SCAN, SCAN_BS>>>();                                       // slot 1
    k_mma<<<(N_NODES + 127) / 128, 256, msm>>>(attn_l, attn_r);             // slot 2
    k_logit<<<(N_EDGES + 255) / 256, 256>>>(feats_edge, src, dst, attn_e);  // slot 3 (PROFILED)
    k_node<<<(N_NODES * 32 + 255) / 256, 256>>>(out);                       // slot 4
}

// round 15
// speedup vs baseline: 1.8025x; 1.0671x over previous
#include <cuda_runtime.h>
#include <cuda_bf16.h>

#define N_NODES 50000
#define N_EDGES 800000
#define IN_DIM  128
#define HD      128   // N_HEAD * OUT_DIM
#define NHEAD   4
#define IN_E    16

#define SCAN_BS 512
#define NBLK_SCAN ((N_NODES + SCAN_BS - 1) / SCAN_BS)   // 98

typedef unsigned int u32;
typedef unsigned long long ull;

// ---------------- scratch (__device__ globals; alloc-free rule) ----------------
__device__ float g_featn[(size_t)N_NODES * HD];
__device__ float g_el[N_NODES * NHEAD];
__device__ float g_er[N_NODES * NHEAD];
__device__ float g_lgs[(size_t)N_EDGES * NHEAD];  // leaky-relu logits, CSR order
__device__ int   g_srcs[N_EDGES];                 // src node per CSR slot
__device__ int   g_cnt[N_NODES];                  // in-degree histogram (zeroed by k_node)
__device__ int   g_off[N_NODES + 1];
__device__ int   g_cur[N_NODES];
__device__ int   g_tilectr;
__device__ ull   g_tstat[NBLK_SCAN];
// bf16-split GEMM operands
__device__ ull   g_xil[(size_t)N_NODES * 64];     // per row: 64 u64 = {hi bf16 pair | lo bf16 pair}
__device__ u32   g_whi[128 * 64];                 // W hi, packed bf16 pairs
__device__ u32   g_wlo[128 * 64];                 // W lo

// ---------------- bf16 split helpers ----------------
__device__ __forceinline__ void split1(float x, unsigned short& h, unsigned short& l) {
    __nv_bfloat16 hb = __float2bfloat16(x);
    float r = x - __bfloat162float(hb);
    __nv_bfloat16 lb = __float2bfloat16(r);
    h = __bfloat16_as_ushort(hb);
    l = __bfloat16_as_ushort(lb);
}
__device__ __forceinline__ void split2(float a, float b, u32& hi, u32& lo) {
    unsigned short ha, la, hb, lb;
    split1(a, ha, la); split1(b, hb, lb);
    hi = (u32)ha | ((u32)hb << 16);
    lo = (u32)la | ((u32)lb << 16);
}

// ---------------- K0 (slot 0): cvt X/W to bf16 hi/lo + histogram + state init ----------------
#define XQUADS (N_NODES * IN_DIM / 4)   // 1,600,000
__global__ void k_prep(const float* __restrict__ x, const float* __restrict__ W,
                       const int* __restrict__ dst) {
    int i = blockIdx.x * blockDim.x + threadIdx.x;
    if (i == 0) g_tilectr = 0;
    if (i < NBLK_SCAN) g_tstat[i] = 0ull;
    if (i < N_EDGES) atomicAdd(&g_cnt[dst[i]], 1);
    if (i < XQUADS) {
        float4 v = ((const float4*)x)[i];
        u32 h0, l0, h1, l1;
        split2(v.x, v.y, h0, l0);
        split2(v.z, v.w, h1, l1);
        g_xil[(size_t)i * 2]     = (ull)h0 | ((ull)l0 << 32);
        g_xil[(size_t)i * 2 + 1] = (ull)h1 | ((ull)l1 << 32);
    } else {
        int j = i - XQUADS;
        if (j < 128 * 128 / 4) {
            float4 v = ((const float4*)W)[j];
            u32 h0, l0, h1, l1;
            split2(v.x, v.y, h0, l0);
            split2(v.z, v.w, h1, l1);
            g_whi[j * 2] = h0;     g_wlo[j * 2] = l0;
            g_whi[j * 2 + 1] = h1; g_wlo[j * 2 + 1] = l1;
        }
    }
}

// ---------------- K1 (slot 1): single-pass decoupled-lookback exclusive scan ----------------
__global__ void k_scan() {
    __shared__ int stile;
    __shared__ int swarp[16];
    __shared__ int sprefix;
    int t = threadIdx.x;
    if (t == 0) stile = atomicAdd(&g_tilectr, 1);
    __syncthreads();
    int tile = stile;
    int i = tile * SCAN_BS + t;
    int v = (i < N_NODES) ? g_cnt[i] : 0;

    int lane = t & 31, wid = t >> 5;
    int xv = v;
    #pragma unroll
    for (int o = 1; o < 32; o <<= 1) {
        int u = __shfl_up_sync(0xffffffffu, xv, o);
        if (lane >= o) xv += u;
    }
    if (lane == 31) swarp[wid] = xv;
    __syncthreads();
    if (wid == 0) {
        int y = (lane < 16) ? swarp[lane] : 0;
        #pragma unroll
        for (int o = 1; o < 16; o <<= 1) {
            int u = __shfl_up_sync(0xffffffffu, y, o);
            if (lane >= o) y += u;
        }
        if (lane < 16) swarp[lane] = y;
    }
    __syncthreads();
    int incl = xv + (wid ? swarp[wid - 1] : 0);
    int total = swarp[15];

    if (t == 0) {
        if (tile == 0) {
            __threadfence();
            atomicExch(&g_tstat[0], (2ull << 32) | (unsigned)total);
            sprefix = 0;
        } else {
            __threadfence();
            atomicExch(&g_tstat[tile], (1ull << 32) | (unsigned)total);
            int excl = 0;
            for (int tb = tile - 1; tb >= 0;) {
                ull s;
                do { s = atomicAdd(&g_tstat[tb], 0ull); } while ((s >> 32) == 0ull);
                excl += (int)(unsigned)s;
                if ((s >> 32) == 2ull) break;
                tb--;
            }
            __threadfence();
            atomicExch(&g_tstat[tile], (2ull << 32) | (unsigned)(excl + total));
            sprefix = excl;
        }
    }
    __syncthreads();
    int pre = sprefix;
    if (i < N_NODES) {
        int off = pre + incl - v;
        g_off[i] = off;
        g_cur[i] = off;
    }
    if (i == N_NODES - 1) g_off[N_NODES] = pre + incl;
}

// ---------------- K2 (slot 2): tensor-core GEMM + fused el/er epilogue ----------------
__device__ __forceinline__ void mma_bf16(float c[4], const u32 a[4], u32 b0, u32 b1) {
    asm volatile(
        "mma.sync.aligned.m16n8k16.row.col.f32.bf16.bf16.f32 "
        "{%0,%1,%2,%3},{%4,%5,%6,%7},{%8,%9},{%0,%1,%2,%3};"
        : "+f"(c[0]), "+f"(c[1]), "+f"(c[2]), "+f"(c[3])
        : "r"(a[0]), "r"(a[1]), "r"(a[2]), "r"(a[3]), "r"(b0), "r"(b1));
}

__global__ void __launch_bounds__(256, 2)
k_mma(const float* __restrict__ al, const float* __restrict__ ar) {
    extern __shared__ u32 smw[];
    u32* WH = smw;                  // [128][68]
    u32* WL = smw + 128 * 68;
    int tid = threadIdx.x;
    for (int i = tid; i < 128 * 64; i += 256) {
        int r = i >> 6, p = i & 63;
        WH[r * 68 + p] = g_whi[i];
        WL[r * 68 + p] = g_wlo[i];
    }
    __syncthreads();

    int warp = tid >> 5, lane = tid & 31;
    int g = lane >> 2, t = lane & 3;
    int mw = warp >> 1, nw = warp & 1;
    int m0 = blockIdx.x * 128 + mw * 32;
    int n0 = nw * 64;

    int r1a = m0 + g;       if (r1a >= N_NODES) r1a = N_NODES - 1;
    int r2a = r1a + 8;      if (r2a >= N_NODES) r2a = N_NODES - 1;
    int r1b = m0 + 16 + g;  if (r1b >= N_NODES) r1b = N_NODES - 1;
    int r2b = r1b + 8;      if (r2b >= N_NODES) r2b = N_NODES - 1;
    const ull* pr[4] = { g_xil + (size_t)r1a * 64 + t, g_xil + (size_t)r2a * 64 + t,
                         g_xil + (size_t)r1b * 64 + t, g_xil + (size_t)r2b * 64 + t };

    float c[2][8][4];
    #pragma unroll
    for (int mi = 0; mi < 2; mi++)
        #pragma unroll
        for (int nf = 0; nf < 8; nf++)
            #pragma unroll
            for (int q = 0; q < 4; q++) c[mi][nf][q] = 0.0f;

    u32 ahi[2][4], alo[2][4];
    #pragma unroll
    for (int mi = 0; mi < 2; mi++) {
        ull A0 = pr[mi*2][0], A1 = pr[mi*2+1][0], A2 = pr[mi*2][4], A3 = pr[mi*2+1][4];
        ahi[mi][0] = (u32)A0; alo[mi][0] = (u32)(A0 >> 32);
        ahi[mi][1] = (u32)A1; alo[mi][1] = (u32)(A1 >> 32);
        ahi[mi][2] = (u32)A2; alo[mi][2] = (u32)(A2 >> 32);
        ahi[mi][3] = (u32)A3; alo[mi][3] = (u32)(A3 >> 32);
    }

    for (int ks = 0; ks < 8; ks++) {
        u32 nhi[2][4], nlo[2][4];
        if (ks < 7) {
            int o = (ks + 1) * 8;
            #pragma unroll
            for (int mi = 0; mi < 2; mi++) {
                ull A0 = pr[mi*2][o], A1 = pr[mi*2+1][o], A2 = pr[mi*2][o+4], A3 = pr[mi*2+1][o+4];
                nhi[mi][0] = (u32)A0; nlo[mi][0] = (u32)(A0 >> 32);
                nhi[mi][1] = (u32)A1; nlo[mi][1] = (u32)(A1 >> 32);
                nhi[mi][2] = (u32)A2; nlo[mi][2] = (u32)(A2 >> 32);
                nhi[mi][3] = (u32)A3; nlo[mi][3] = (u32)(A3 >> 32);
            }
        }
        #pragma unroll
        for (int nf = 0; nf < 8; nf++) {
            int n = n0 + nf * 8 + g;
            int bi = n * 68 + ks * 8 + t;
            u32 bh0 = WH[bi], bh1 = WH[bi + 4];
            u32 bl0 = WL[bi], bl1 = WL[bi + 4];
            mma_bf16(c[0][nf], ahi[0], bh0, bh1);
            mma_bf16(c[1][nf], ahi[1], bh0, bh1);
            mma_bf16(c[0][nf], alo[0], bh0, bh1);
            mma_bf16(c[1][nf], alo[1], bh0, bh1);
            mma_bf16(c[0][nf], ahi[0], bl0, bl1);
            mma_bf16(c[1][nf], ahi[1], bl0, bl1);
        }
        #pragma unroll
        for (int mi = 0; mi < 2; mi++)
            #pragma unroll
            for (int q = 0; q < 4; q++) { ahi[mi][q] = nhi[mi][q]; alo[mi][q] = nlo[mi][q]; }
    }

    #pragma unroll
    for (int mi = 0; mi < 2; mi++) {
        int r1 = m0 + mi * 16 + g;
        int r2 = r1 + 8;
        #pragma unroll
        for (int nf = 0; nf < 8; nf++) {
            int col = n0 + nf * 8 + 2 * t;
            if (r1 < N_NODES)
                *(float2*)&g_featn[(size_t)r1 * HD + col] = make_float2(c[mi][nf][0], c[mi][nf][1]);
            if (r2 < N_NODES)
                *(float2*)&g_featn[(size_t)r2 * HD + col] = make_float2(c[mi][nf][2], c[mi][nf][3]);
        }
    }

    // fused el/er epilogue
    #pragma unroll
    for (int mi = 0; mi < 2; mi++) {
        #pragma unroll
        for (int hh = 0; hh < 2; hh++) {
            float p1l = 0.f, p2l = 0.f, p1r = 0.f, p2r = 0.f;
            #pragma unroll
            for (int nf = hh * 4; nf < hh * 4 + 4; nf++) {
                int col = n0 + nf * 8 + 2 * t;
                float a0v = al[col], a1v = al[col + 1];
                float b0v = ar[col], b1v = ar[col + 1];
                p1l += c[mi][nf][0] * a0v + c[mi][nf][1] * a1v;
                p2l += c[mi][nf][2] * a0v + c[mi][nf][3] * a1v;
                p1r += c[mi][nf][0] * b0v + c[mi][nf][1] * b1v;
                p2r += c[mi][nf][2] * b0v + c[mi][nf][3] * b1v;
            }
            #pragma unroll
            for (int o = 1; o <= 2; o <<= 1) {
                p1l += __shfl_xor_sync(0xffffffffu, p1l, o);
                p2l += __shfl_xor_sync(0xffffffffu, p2l, o);
                p1r += __shfl_xor_sync(0xffffffffu, p1r, o);
                p2r += __shfl_xor_sync(0xffffffffu, p2r, o);
            }
            if (t == 0) {
                int head = 2 * nw + hh;
                int r1 = m0 + mi * 16 + g;
                int r2 = r1 + 8;
                if (r1 < N_NODES) { g_el[r1 * NHEAD + head] = p1l; g_er[r1 * NHEAD + head] = p1r; }
                if (r2 < N_NODES) { g_el[r2 * NHEAD + head] = p2l; g_er[r2 * NHEAD + head] = p2r; }
            }
        }
    }
}

// ---------------- K3 (slot 3, PROFILED): edge logits + CSR scatter (cursor atomic only) ----------------
__global__ void k_logit(const float* __restrict__ fe, const int* __restrict__ src,
                        const int* __restrict__ dst, const float* __restrict__ ae) {
    __shared__ float aesm[NHEAD * IN_E];
    if (threadIdx.x < NHEAD * IN_E) aesm[threadIdx.x] = ae[threadIdx.x];
    __syncthreads();
    int e = blockIdx.x * blockDim.x + threadIdx.x;
    if (e >= N_EDGES) return;
    int s = src[e], d = dst[e];
    int pos = atomicAdd(&g_cur[d], 1);                  // issue early: latency overlaps the math

    const float4* fr = (const float4*)(fe + (size_t)e * IN_E);
    float4 f0 = fr[0], f1 = fr[1], f2 = fr[2], f3 = fr[3];
    float4 elv = *(const float4*)(g_el + s * NHEAD);
    float4 erv = *(const float4*)(g_er + d * NHEAD);
    float els[4] = {elv.x, elv.y, elv.z, elv.w};
    float ers[4] = {erv.x, erv.y, erv.z, erv.w};

    float lg[4];
    #pragma unroll
    for (int h = 0; h < NHEAD; h++) {
        const float* a = aesm + h * IN_E;
        float ee = f0.x*a[0]  + f0.y*a[1]  + f0.z*a[2]  + f0.w*a[3]
                 + f1.x*a[4]  + f1.y*a[5]  + f1.z*a[6]  + f1.w*a[7]
                 + f2.x*a[8]  + f2.y*a[9]  + f2.z*a[10] + f2.w*a[11]
                 + f3.x*a[12] + f3.y*a[13] + f3.z*a[14] + f3.w*a[15];
        float v = els[h] + ers[h] + ee;
        lg[h] = v > 0.0f ? v : 0.2f * v;                // leaky relu 0.2
    }
    ((float4*)g_lgs)[pos] = make_float4(lg[0], lg[1], lg[2], lg[3]);
    g_srcs[pos] = s;
}

// ---------------- K4: per-dst-node softmax + weighted aggregate ----------------
// pass 1: coalesced max over CSR logits; pass 2: merged exp-sum + gather-accumulate.
__global__ void k_node(float* __restrict__ out) {
    int w = (blockIdx.x * blockDim.x + threadIdx.x) >> 5;
    if (w >= N_NODES) return;
    int lane = threadIdx.x & 31;
    if (lane == 0) g_cnt[w] = 0;                        // restore invariant for next run
    int c = lane * 4, h = lane >> 3;
    float* orow = out + (size_t)w * HD + c;

    int beg = g_off[w], end = g_off[w + 1];
    if (beg == end) {
        *(float4*)orow = make_float4(0.f, 0.f, 0.f, 0.f);
        return;
    }
    // pass 1: per-head max (coalesced sequential float4 loads)
    const float NEG = -3.4e38f;
    float4 mx = make_float4(NEG, NEG, NEG, NEG);
    for (int p = beg + lane; p < end; p += 32) {
        float4 lg = ((const float4*)g_lgs)[p];
        mx.x = fmaxf(mx.x, lg.x); mx.y = fmaxf(mx.y, lg.y);
        mx.z = fmaxf(mx.z, lg.z); mx.w = fmaxf(mx.w, lg.w);
    }
    #pragma unroll
    for (int o = 16; o; o >>= 1) {
        mx.x = fmaxf(mx.x, __shfl_xor_sync(0xffffffffu, mx.x, o));
        mx.y = fmaxf(mx.y, __shfl_xor_sync(0xffffffffu, mx.y, o));
        mx.z = fmaxf(mx.z, __shfl_xor_sync(0xffffffffu, mx.z, o));
        mx.w = fmaxf(mx.w, __shfl_xor_sync(0xffffffffu, mx.w, o));
    }
    float mh = (h == 0) ? mx.x : (h == 1) ? mx.y : (h == 2) ? mx.z : mx.w;

    // pass 2: merged exp-sum + weighted gather, 2 ILP chains
    float sh0 = 0.f, sh1 = 0.f;
    float4 a0 = make_float4(0.f, 0.f, 0.f, 0.f);
    float4 a1 = make_float4(0.f, 0.f, 0.f, 0.f);
    const float* fb = g_featn + c;
    int p = beg;
    while (p < end) {
        int cnt = end - p; if (cnt > 32) cnt = 32;
        int sv = g_srcs[p + (lane < cnt ? lane : 0)];
        int j = 0;
        for (; j + 2 <= cnt; j += 2) {
            int s0 = __shfl_sync(0xffffffffu, sv, j);
            int s1 = __shfl_sync(0xffffffffu, sv, j + 1);
            float lg0 = g_lgs[(p + j) * NHEAD + h];
            float lg1 = g_lgs[(p + j + 1) * NHEAD + h];
            float4 f0 = *(const float4*)(fb + s0 * HD);
            float4 f1 = *(const float4*)(fb + s1 * HD);
            float e0 = __expf(lg0 - mh);
            float e1 = __expf(lg1 - mh);
            sh0 += e0; sh1 += e1;
            a0.x += e0 * f0.x; a0.y += e0 * f0.y; a0.z += e0 * f0.z; a0.w += e0 * f0.w;
            a1.x += e1 * f1.x; a1.y += e1 * f1.y; a1.z += e1 * f1.z; a1.w += e1 * f1.w;
        }
        if (j < cnt) {
            int s0 = __shfl_sync(0xffffffffu, sv, j);
            float lg0 = g_lgs[(p + j) * NHEAD + h];
            float4 f0 = *(const float4*)(fb + s0 * HD);
            float e0 = __expf(lg0 - mh);
            sh0 += e0;
            a0.x += e0 * f0.x; a0.y += e0 * f0.y; a0.z += e0 * f0.z; a0.w += e0 * f0.w;
        }
        p += cnt;
    }
    float inv = 1.0f / (sh0 + sh1);
    float4 acc = make_float4((a0.x + a1.x) * inv, (a0.y + a1.y) * inv,
                             (a0.z + a1.z) * inv, (a0.w + a1.w) * inv);
    *(float4*)orow = acc;
}

// ---------------- launch ----------------
extern "C" void kernel_launch(void* const* d_in, const int* in_sizes, int n_in,
                              void* d_out, int out_size) {
    const float* feats_node = (const float*)d_in[0];
    const float* feats_edge = (const float*)d_in[1];
    const int*   src        = (const int*)d_in[2];
    const int*   dst        = (const int*)d_in[3];
    const float* W_node     = (const float*)d_in[4];
    const float* attn_l     = (const float*)d_in[5];
    const float* attn_r     = (const float*)d_in[6];
    const float* attn_e     = (const float*)d_in[7];
    float* out = (float*)d_out;

    int msm = 2 * 128 * 68 * sizeof(u32);               // 69632 B
    static int configured = 0;
    if (!configured) {
        cudaFuncSetAttribute(k_mma, cudaFuncAttributeMaxDynamicSharedMemorySize, msm);
        configured = 1;
    }

    int prep_threads = XQUADS + 128 * 128 / 4;
    k_prep<<<(prep_threads + 255) / 256, 256>>>(feats_node, W_node, dst);   // slot 0
    k_scan<<<NBLK_SCAN, SCAN_BS>>>();                                       // slot 1
    k_mma<<<(N_NODES + 127) / 128, 256, msm>>>(attn_l, attn_r);             // slot 2
    k_logit<<<(N_EDGES + 255) / 256, 256>>>(feats_edge, src, dst, attn_e);  // slot 3 (PROFILED)
    k_node<<<(N_NODES * 32 + 255) / 256, 256>>>(out);                       // slot 4
}